// round 6
// baseline (speedup 1.0000x reference)
#include <cuda_runtime.h>
#include <cstdint>

#define N_NODES 100000
#define N_EDGES 20000
#define NNZ     1000000
#define D       64
#define ESTRIDE 112          // max incidences per edge bin (Poisson(50), ~9 sigma)
#define VSTRIDE 40           // max incidences per vertex bin (Poisson(10), ~9 sigma)

// ---------------- scratch (device globals; allocation-free) ----------------
__device__ float g_Z   [N_EDGES * D];       // Xsum @ W1Bf + deg*bZ
__device__ int   g_cur_e[N_EDGES];          // edge incidence count (true deg)
__device__ int   g_cur_v[N_NODES];          // vertex incidence count (true deg)
__device__ int   g_adj_e[N_EDGES * ESTRIDE];
__device__ int   g_adj_v[N_NODES * VSTRIDE];
__device__ float g_W1T [D * D];             // W1_w transposed [k][j]
__device__ float g_W1Bf[D * D];             // W1T @ Bf
__device__ float g_bZ  [D];                 // b1 @ Bf
__device__ float g_WcatA[128 * D];          // [A | W^T] stacked, [k][j]
__device__ float g_cvec[D];                 // b2 @ W^T

// ---------------------------------------------------------------------------
// k_pre_all (single block): all weight folding.
//   WT[m][j]   = W_w[j][m]
//   A          = W2a^T @ WT          -> g_WcatA[0:64]
//   WT         -> g_WcatA[64:128]
//   Bf         = W2b^T @ WT          (smem only)
//   W1T[k][j]  = W1_w[j][k]          -> g_W1T
//   W1Bf       = W1T @ Bf            -> g_W1Bf
//   bZ         = b1 @ Bf             -> g_bZ
//   cvec       = b2 @ WT             -> g_cvec
// ---------------------------------------------------------------------------
__global__ __launch_bounds__(256) void k_pre_all(const float* __restrict__ W1_w,
                                                 const float* __restrict__ W1_b,
                                                 const float* __restrict__ W2_w,
                                                 const float* __restrict__ W2_b,
                                                 const float* __restrict__ W_w) {
    __shared__ float WT [64 * 64];
    __shared__ float Bfs[64 * 64];
    __shared__ float W1Ts[64 * 64];
    int tid = threadIdx.x;
    for (int i = tid; i < 4096; i += 256) {
        int j = i >> 6, m = i & 63;
        WT[m * 64 + j] = W_w[i];
        int k = i >> 6;  // for W1T: i = j*64+k form
        (void)k;
        W1Ts[(i & 63) * 64 + (i >> 6)] = W1_w[i];   // W1Ts[k][j] = W1_w[j][k]
    }
    __syncthreads();
    // A, Bf, WT copy, W1T store, cvec
    for (int i = tid; i < 4096; i += 256) {
        int k = i >> 6, j = i & 63;
        float accA = 0.f, accB = 0.f;
        #pragma unroll 8
        for (int m = 0; m < 64; m++) {
            float wt = WT[m * 64 + j];
            accA += W2_w[m * 128 + k] * wt;
            accB += W2_w[m * 128 + 64 + k] * wt;
        }
        g_WcatA[i] = accA;
        Bfs[i] = accB;
        g_WcatA[4096 + i] = WT[i];
        g_W1T[i] = W1Ts[i];
    }
    if (tid < 64) {
        float acc = 0.f, accz = 0.f;
        for (int m = 0; m < 64; m++) acc += W2_b[m] * WT[m * 64 + tid];
        g_cvec[tid] = acc;
        (void)accz;
    }
    __syncthreads();
    // W1Bf = W1Ts @ Bfs ; bZ = b1 @ Bfs
    for (int i = tid; i < 4096; i += 256) {
        int k = i >> 6, j = i & 63;
        float acc = 0.f;
        #pragma unroll 8
        for (int m = 0; m < 64; m++) acc += W1Ts[k * 64 + m] * Bfs[m * 64 + j];
        g_W1Bf[i] = acc;
    }
    if (tid < 64) {
        float acc = 0.f;
        for (int m = 0; m < 64; m++) acc += W1_b[m] * Bfs[m * 64 + tid];
        g_bZ[tid] = acc;
    }
}

// ---------------------------------------------------------------------------
// k_fill: fixed-stride binning, 2 incidences per thread.
// ---------------------------------------------------------------------------
__global__ __launch_bounds__(256) void k_fill(const int* __restrict__ vertex,
                                              const int* __restrict__ edges) {
    int i = blockIdx.x * 256 + threadIdx.x;
    if (i * 2 >= NNZ) return;
    int2 v2 = __ldg((const int2*)vertex + i);
    int2 e2 = __ldg((const int2*)edges + i);
    int se0 = atomicAdd(&g_cur_e[e2.x], 1);
    if (se0 < ESTRIDE) g_adj_e[e2.x * ESTRIDE + se0] = v2.x;
    int sv0 = atomicAdd(&g_cur_v[v2.x], 1);
    if (sv0 < VSTRIDE) g_adj_v[v2.x * VSTRIDE + sv0] = e2.x;
    int se1 = atomicAdd(&g_cur_e[e2.y], 1);
    if (se1 < ESTRIDE) g_adj_e[e2.y * ESTRIDE + se1] = v2.y;
    int sv1 = atomicAdd(&g_cur_v[v2.y], 1);
    if (sv1 < VSTRIDE) g_adj_v[v2.y * VSTRIDE + sv1] = e2.y;
}

// float4 gather-accumulate helper (unroll 4)
__device__ __forceinline__ float4 gather_rows(const int* __restrict__ adj, int d,
                                              const float4* __restrict__ S4,
                                              int lane) {
    float4 acc = make_float4(0.f, 0.f, 0.f, 0.f);
    int j = 0;
    for (; j + 4 <= d; j += 4) {
        int a0 = __ldg(adj + j + 0);
        int a1 = __ldg(adj + j + 1);
        int a2 = __ldg(adj + j + 2);
        int a3 = __ldg(adj + j + 3);
        float4 x0 = S4[(size_t)a0 * 16 + lane];
        float4 x1 = S4[(size_t)a1 * 16 + lane];
        float4 x2 = S4[(size_t)a2 * 16 + lane];
        float4 x3 = S4[(size_t)a3 * 16 + lane];
        acc.x += (x0.x + x1.x) + (x2.x + x3.x);
        acc.y += (x0.y + x1.y) + (x2.y + x3.y);
        acc.z += (x0.z + x1.z) + (x2.z + x3.z);
        acc.w += (x0.w + x1.w) + (x2.w + x3.w);
    }
    for (; j < d; j++) {
        int a0 = __ldg(adj + j);
        float4 x0 = S4[(size_t)a0 * 16 + lane];
        acc.x += x0.x; acc.y += x0.y; acc.z += x0.z; acc.w += x0.w;
    }
    return acc;
}

// ---------------------------------------------------------------------------
// k_edge_fused: gather Xsum for a 32-edge tile directly into smem, then two
// independent GEMMs:
//   Xe = Xsum @ W1T  + deg_e*b1  -> XeOut (d_out)
//   Z  = Xsum @ W1Bf + deg_e*bZ  -> g_Z
// 256 threads; 16 half-warps gather 2 edges each; GEMM: 2 rows x 4 cols x 2.
// ---------------------------------------------------------------------------
__global__ __launch_bounds__(256) void k_edge_fused(const float* __restrict__ X,
                                                    const float* __restrict__ b1,
                                                    float* __restrict__ XeOut) {
    __shared__ float Xs[64][34];    // [k][r]
    __shared__ float W1s[64][64];
    __shared__ float W2s[64][64];
    __shared__ float bs[64], bzs[64], degs[32];
    int tid = threadIdx.x;
    int row0 = blockIdx.x * 32;

    for (int i = tid; i < 1024; i += 256) {
        ((float4*)W1s)[i] = ((const float4*)g_W1T)[i];
        ((float4*)W2s)[i] = ((const float4*)g_W1Bf)[i];
    }
    if (tid < 64) {
        bs[tid] = b1[tid];
        bzs[tid] = g_bZ[tid];
    } else if (tid < 96) {
        int r = row0 + tid - 64;
        degs[tid - 64] = (r < N_EDGES) ? (float)min(g_cur_e[r], ESTRIDE) : 0.f;
    }

    // gather phase: half-warp hw handles edges r = hw*2, hw*2+1
    int hw = tid >> 4, lane = tid & 15;
    const float4* X4 = (const float4*)X;
    #pragma unroll
    for (int sub = 0; sub < 2; sub++) {
        int r = hw * 2 + sub;
        int seg = row0 + r;
        float4 acc = make_float4(0.f, 0.f, 0.f, 0.f);
        if (seg < N_EDGES) {
            int d = g_cur_e[seg];
            if (d > ESTRIDE) d = ESTRIDE;
            acc = gather_rows(g_adj_e + seg * ESTRIDE, d, X4, lane);
        }
        Xs[lane * 4 + 0][r] = acc.x;
        Xs[lane * 4 + 1][r] = acc.y;
        Xs[lane * 4 + 2][r] = acc.z;
        Xs[lane * 4 + 3][r] = acc.w;
    }
    __syncthreads();

    int tx = tid & 15, ty = tid >> 4;   // 16 x 16
    int tx4 = tx * 4, ty2 = ty * 2;
    float a1[2][4] = {}, a2[2][4] = {};
    #pragma unroll 16
    for (int k = 0; k < 64; k++) {
        float2 a = *(const float2*)&Xs[k][ty2];
        float4 w1 = *(const float4*)&W1s[k][tx4];
        float4 w2 = *(const float4*)&W2s[k][tx4];
        a1[0][0] += a.x * w1.x; a1[0][1] += a.x * w1.y;
        a1[0][2] += a.x * w1.z; a1[0][3] += a.x * w1.w;
        a1[1][0] += a.y * w1.x; a1[1][1] += a.y * w1.y;
        a1[1][2] += a.y * w1.z; a1[1][3] += a.y * w1.w;
        a2[0][0] += a.x * w2.x; a2[0][1] += a.x * w2.y;
        a2[0][2] += a.x * w2.z; a2[0][3] += a.x * w2.w;
        a2[1][0] += a.y * w2.x; a2[1][1] += a.y * w2.y;
        a2[1][2] += a.y * w2.z; a2[1][3] += a.y * w2.w;
    }
    #pragma unroll
    for (int r = 0; r < 2; r++) {
        int row = row0 + ty2 + r;
        if (row < N_EDGES) {
            float dg = degs[ty2 + r];
            float4 xe = make_float4(a1[r][0] + dg * bs[tx4 + 0],
                                    a1[r][1] + dg * bs[tx4 + 1],
                                    a1[r][2] + dg * bs[tx4 + 2],
                                    a1[r][3] + dg * bs[tx4 + 3]);
            float4 z  = make_float4(a2[r][0] + dg * bzs[tx4 + 0],
                                    a2[r][1] + dg * bzs[tx4 + 1],
                                    a2[r][2] + dg * bzs[tx4 + 2],
                                    a2[r][3] + dg * bzs[tx4 + 3]);
            ((float4*)XeOut)[(size_t)row * 16 + tx] = xe;
            ((float4*)g_Z)[(size_t)row * 16 + tx]   = z;
        }
    }
}

// ---------------------------------------------------------------------------
// k_node_fused: gather 0.5*sum(Z) for a 128-node tile into smem stage,
// preload into f32x2 accumulators, then:
// out = 0.5*deg*(X@A) + 0.5*(X0@W^T) + [0.5*SZ] + 0.5*deg*cvec + Wb
// ---------------------------------------------------------------------------
#define FMA_X2(d, a, b) \
    asm("fma.rn.f32x2 %0, %1, %2, %0;" : "+l"(d) : "l"(a), "l"(b))

#define XS_STRIDE 132   // floats per k-row; multiple of 4 -> 16B alignment kept

__global__ __launch_bounds__(256) void k_node_fused(const float* __restrict__ X,
                                                    const float* __restrict__ X0,
                                                    const float* __restrict__ Wb,
                                                    float* __restrict__ out) {
    extern __shared__ char sm_raw[];
    float* Xs = (float*)sm_raw;                                        // [64][132] (also SZ stage)
    unsigned long long* Wd =
        (unsigned long long*)(sm_raw + 64 * XS_STRIDE * 4);            // [64][64] dup pairs
    float* degs = (float*)(sm_raw + 64 * XS_STRIDE * 4 + 64 * 64 * 8); // [128] = 0.5*deg
    float* cv   = degs + 128;                                          // [64]
    float* bb   = cv + 64;                                             // [64]

    int tid = threadIdx.x;
    int row0 = blockIdx.x * 128;

    if (tid < 128) {
        int r = row0 + tid;
        degs[tid] = (r < N_NODES) ? 0.5f * (float)min(g_cur_v[r], VSTRIDE) : 0.f;
    } else if (tid < 192) {
        cv[tid - 128] = g_cvec[tid - 128];
    } else {
        bb[tid - 192] = Wb[tid - 192];
    }

    // ---- gather phase: stage[r][c] = 0.5 * sum(Z rows) ----
    int hw = tid >> 4, lane = tid & 15;
    const float4* Z4 = (const float4*)g_Z;
    float* stage = Xs;   // 128*64 = 8192 floats <= 64*132 = 8448
    #pragma unroll
    for (int s = 0; s < 8; s++) {
        int r = hw + s * 16;           // 0..127
        int node = row0 + r;
        float4 acc = make_float4(0.f, 0.f, 0.f, 0.f);
        if (node < N_NODES) {
            int d = g_cur_v[node];
            if (d > VSTRIDE) d = VSTRIDE;
            acc = gather_rows(g_adj_v + node * VSTRIDE, d, Z4, lane);
        }
        acc.x *= 0.5f; acc.y *= 0.5f; acc.z *= 0.5f; acc.w *= 0.5f;
        ((float4*)(stage + r * 64))[lane] = acc;
    }
    __syncthreads();

    int tx = tid & 15, ty = tid >> 4;
    int tx4 = tx * 4, ty8 = ty * 8;

    // ---- preload accumulators with 0.5*SZ ----
    unsigned long long acc[4][4];
    #pragma unroll
    for (int p = 0; p < 4; p++) {
        int rl = ty8 + 2 * p;
        #pragma unroll
        for (int c = 0; c < 4; c++) {
            float lo = stage[rl * 64 + tx4 + c];
            float hi = stage[(rl + 1) * 64 + tx4 + c];
            asm("mov.b64 %0, {%1, %2};" : "=l"(acc[p][c]) : "f"(lo), "f"(hi));
        }
    }
    __syncthreads();   // stage reads done before Xs reuse

    #pragma unroll
    for (int kb = 0; kb < 2; kb++) {
        const float* src = (kb == 0) ? X : X0;
        #pragma unroll
        for (int i = 0; i < 8; i++) {
            int f = tid + i * 256;
            int r = f >> 4, k4 = f & 15;
            int row = row0 + r;
            float s = (kb == 0) ? degs[r] : 0.5f;
            float4 x = (row < N_NODES) ? ((const float4*)src)[row * 16 + k4]
                                       : make_float4(0.f, 0.f, 0.f, 0.f);
            Xs[(k4 * 4 + 0) * XS_STRIDE + r] = s * x.x;
            Xs[(k4 * 4 + 1) * XS_STRIDE + r] = s * x.y;
            Xs[(k4 * 4 + 2) * XS_STRIDE + r] = s * x.z;
            Xs[(k4 * 4 + 3) * XS_STRIDE + r] = s * x.w;
        }
        for (int i = tid; i < 4096; i += 256) {
            float w = g_WcatA[kb * 4096 + i];
            ((float2*)Wd)[i] = make_float2(w, w);
        }
        __syncthreads();

        #pragma unroll 8
        for (int k = 0; k < 64; k++) {
            ulonglong2 a01 = *(const ulonglong2*)(Xs + k * XS_STRIDE + ty8);
            ulonglong2 a23 = *(const ulonglong2*)(Xs + k * XS_STRIDE + ty8 + 4);
            ulonglong2 b01 = *(const ulonglong2*)(Wd + k * 64 + tx4);
            ulonglong2 b23 = *(const ulonglong2*)(Wd + k * 64 + tx4 + 2);
            FMA_X2(acc[0][0], a01.x, b01.x); FMA_X2(acc[0][1], a01.x, b01.y);
            FMA_X2(acc[0][2], a01.x, b23.x); FMA_X2(acc[0][3], a01.x, b23.y);
            FMA_X2(acc[1][0], a01.y, b01.x); FMA_X2(acc[1][1], a01.y, b01.y);
            FMA_X2(acc[1][2], a01.y, b23.x); FMA_X2(acc[1][3], a01.y, b23.y);
            FMA_X2(acc[2][0], a23.x, b01.x); FMA_X2(acc[2][1], a23.x, b01.y);
            FMA_X2(acc[2][2], a23.x, b23.x); FMA_X2(acc[2][3], a23.x, b23.y);
            FMA_X2(acc[3][0], a23.y, b01.x); FMA_X2(acc[3][1], a23.y, b01.y);
            FMA_X2(acc[3][2], a23.y, b23.x); FMA_X2(acc[3][3], a23.y, b23.y);
        }
        __syncthreads();
    }

    #pragma unroll
    for (int p = 0; p < 4; p++) {
        float lo[4], hi[4];
        #pragma unroll
        for (int c = 0; c < 4; c++) {
            asm("mov.b64 {%0, %1}, %2;" : "=f"(lo[c]), "=f"(hi[c]) : "l"(acc[p][c]));
        }
        int rl = ty8 + 2 * p;
        int row_lo = row0 + rl;
        int row_hi = row_lo + 1;
        if (row_lo < N_NODES) {
            float hd = degs[rl];
            float4 o;
            o.x = lo[0] + hd * cv[tx4 + 0] + bb[tx4 + 0];
            o.y = lo[1] + hd * cv[tx4 + 1] + bb[tx4 + 1];
            o.z = lo[2] + hd * cv[tx4 + 2] + bb[tx4 + 2];
            o.w = lo[3] + hd * cv[tx4 + 3] + bb[tx4 + 3];
            ((float4*)out)[(size_t)row_lo * 16 + tx] = o;
        }
        if (row_hi < N_NODES) {
            float hd = degs[rl + 1];
            float4 o;
            o.x = hi[0] + hd * cv[tx4 + 0] + bb[tx4 + 0];
            o.y = hi[1] + hd * cv[tx4 + 1] + bb[tx4 + 1];
            o.z = hi[2] + hd * cv[tx4 + 2] + bb[tx4 + 2];
            o.w = hi[3] + hd * cv[tx4 + 3] + bb[tx4 + 3];
            ((float4*)out)[(size_t)row_hi * 16 + tx] = o;
        }
    }
}

#define NODE_SMEM (64 * XS_STRIDE * 4 + 64 * 64 * 8 + 128 * 4 + 64 * 4 + 64 * 4)

// ---------------------------------------------------------------------------
extern "C" void kernel_launch(void* const* d_in, const int* in_sizes, int n_in,
                              void* d_out, int out_size) {
    const float* X      = (const float*)d_in[0];
    const float* X0     = (const float*)d_in[1];
    const int*   vertex = (const int*)d_in[2];
    const int*   edges  = (const int*)d_in[3];
    const float* W1_w   = (const float*)d_in[4];
    const float* W1_b   = (const float*)d_in[5];
    const float* W2_w   = (const float*)d_in[6];
    const float* W2_b   = (const float*)d_in[7];
    const float* W_w    = (const float*)d_in[8];
    const float* W_b    = (const float*)d_in[9];

    float* out   = (float*)d_out;                       // [N_NODES, 64]
    float* XeOut = (float*)d_out + (size_t)N_NODES * D; // [N_EDGES, 64]

    static_assert(NODE_SMEM < 100 * 1024, "smem");
    cudaFuncSetAttribute(k_node_fused, cudaFuncAttributeMaxDynamicSharedMemorySize,
                         NODE_SMEM);

    void *cureP = nullptr, *curvP = nullptr;
    cudaGetSymbolAddress(&cureP, g_cur_e);
    cudaGetSymbolAddress(&curvP, g_cur_v);
    cudaMemsetAsync(cureP, 0, (size_t)N_EDGES * sizeof(int), 0);
    cudaMemsetAsync(curvP, 0, (size_t)N_NODES * sizeof(int), 0);

    k_pre_all<<<1, 256>>>(W1_w, W1_b, W2_w, W2_b, W_w);
    k_fill<<<(NNZ / 2 + 255) / 256, 256>>>(vertex, edges);
    k_edge_fused<<<(N_EDGES + 31) / 32, 256>>>(X, W1_b, XeOut);
    k_node_fused<<<(N_NODES + 127) / 128, 256, NODE_SMEM>>>(X, X0, W_b, out);
}

// round 7
// speedup vs baseline: 1.0517x; 1.0517x over previous
#include <cuda_runtime.h>
#include <cstdint>

#define N_NODES 100000
#define N_EDGES 20000
#define NNZ     1000000
#define D       64
#define ESTRIDE 112          // max incidences per edge bin (Poisson(50), ~9 sigma)
#define VSTRIDE 40           // max incidences per vertex bin (Poisson(10), ~9 sigma)

// ---------------- scratch (device globals; allocation-free) ----------------
__device__ float g_Z   [N_EDGES * D];       // Xsum @ W1Bf + deg*bZ
__device__ float g_SZ  [N_NODES * D];       // per-vertex sum of Z rows
__device__ int   g_cur_e[N_EDGES];          // edge incidence count (true deg)
__device__ int   g_cur_v[N_NODES];          // vertex incidence count (true deg)
__device__ int   g_adj_e[N_EDGES * ESTRIDE];
__device__ int   g_adj_v[N_NODES * VSTRIDE];
__device__ float g_W1T [D * D];             // W1_w transposed [k][j]
__device__ float g_W1Bf[D * D];             // W1T @ Bf
__device__ float g_bZ  [D];                 // b1 @ Bf
__device__ float g_WcatA[128 * D];          // [A | W^T] stacked, [k][j]
__device__ float g_cvec[D];                 // b2 @ W^T

// ---------------------------------------------------------------------------
// k_pre_all (single block): all weight folding.
// ---------------------------------------------------------------------------
__global__ __launch_bounds__(256) void k_pre_all(const float* __restrict__ W1_w,
                                                 const float* __restrict__ W1_b,
                                                 const float* __restrict__ W2_w,
                                                 const float* __restrict__ W2_b,
                                                 const float* __restrict__ W_w) {
    __shared__ float WT [64 * 64];
    __shared__ float Bfs[64 * 64];
    __shared__ float W1Ts[64 * 64];
    int tid = threadIdx.x;
    for (int i = tid; i < 4096; i += 256) {
        int j = i >> 6, m = i & 63;
        WT[m * 64 + j] = W_w[i];
        W1Ts[(i & 63) * 64 + (i >> 6)] = W1_w[i];   // W1Ts[k][j] = W1_w[j][k]
    }
    __syncthreads();
    for (int i = tid; i < 4096; i += 256) {
        int k = i >> 6, j = i & 63;
        float accA = 0.f, accB = 0.f;
        #pragma unroll 8
        for (int m = 0; m < 64; m++) {
            float wt = WT[m * 64 + j];
            accA += W2_w[m * 128 + k] * wt;
            accB += W2_w[m * 128 + 64 + k] * wt;
        }
        g_WcatA[i] = accA;          // A = W2a^T @ W^T
        Bfs[i] = accB;              // Bf = W2b^T @ W^T
        g_WcatA[4096 + i] = WT[i];  // W^T
        g_W1T[i] = W1Ts[i];
    }
    if (tid < 64) {
        float acc = 0.f;
        for (int m = 0; m < 64; m++) acc += W2_b[m] * WT[m * 64 + tid];
        g_cvec[tid] = acc;
    }
    __syncthreads();
    for (int i = tid; i < 4096; i += 256) {
        int k = i >> 6, j = i & 63;
        float acc = 0.f;
        #pragma unroll 8
        for (int m = 0; m < 64; m++) acc += W1Ts[k * 64 + m] * Bfs[m * 64 + j];
        g_W1Bf[i] = acc;            // W1Bf = W1^T @ Bf
    }
    if (tid < 64) {
        float acc = 0.f;
        for (int m = 0; m < 64; m++) acc += W1_b[m] * Bfs[m * 64 + tid];
        g_bZ[tid] = acc;            // bZ = b1 @ Bf
    }
}

// ---------------------------------------------------------------------------
// k_fill: fixed-stride binning, 2 incidences per thread.
// ---------------------------------------------------------------------------
__global__ __launch_bounds__(256) void k_fill(const int* __restrict__ vertex,
                                              const int* __restrict__ edges) {
    int i = blockIdx.x * 256 + threadIdx.x;
    if (i * 2 >= NNZ) return;
    int2 v2 = __ldg((const int2*)vertex + i);
    int2 e2 = __ldg((const int2*)edges + i);
    int se0 = atomicAdd(&g_cur_e[e2.x], 1);
    if (se0 < ESTRIDE) g_adj_e[e2.x * ESTRIDE + se0] = v2.x;
    int sv0 = atomicAdd(&g_cur_v[v2.x], 1);
    if (sv0 < VSTRIDE) g_adj_v[v2.x * VSTRIDE + sv0] = e2.x;
    int se1 = atomicAdd(&g_cur_e[e2.y], 1);
    if (se1 < ESTRIDE) g_adj_e[e2.y * ESTRIDE + se1] = v2.y;
    int sv1 = atomicAdd(&g_cur_v[v2.y], 1);
    if (sv1 < VSTRIDE) g_adj_v[v2.y * VSTRIDE + sv1] = e2.y;
}

// float4 gather-accumulate helper (unroll 4)
__device__ __forceinline__ float4 gather_rows(const int* __restrict__ adj, int d,
                                              const float4* __restrict__ S4,
                                              int lane) {
    float4 acc = make_float4(0.f, 0.f, 0.f, 0.f);
    int j = 0;
    for (; j + 4 <= d; j += 4) {
        int a0 = __ldg(adj + j + 0);
        int a1 = __ldg(adj + j + 1);
        int a2 = __ldg(adj + j + 2);
        int a3 = __ldg(adj + j + 3);
        float4 x0 = S4[(size_t)a0 * 16 + lane];
        float4 x1 = S4[(size_t)a1 * 16 + lane];
        float4 x2 = S4[(size_t)a2 * 16 + lane];
        float4 x3 = S4[(size_t)a3 * 16 + lane];
        acc.x += (x0.x + x1.x) + (x2.x + x3.x);
        acc.y += (x0.y + x1.y) + (x2.y + x3.y);
        acc.z += (x0.z + x1.z) + (x2.z + x3.z);
        acc.w += (x0.w + x1.w) + (x2.w + x3.w);
    }
    for (; j < d; j++) {
        int a0 = __ldg(adj + j);
        float4 x0 = S4[(size_t)a0 * 16 + lane];
        acc.x += x0.x; acc.y += x0.y; acc.z += x0.z; acc.w += x0.w;
    }
    return acc;
}

// ---------------------------------------------------------------------------
// k_edge_fused: gather Xsum for a 32-edge tile directly into smem, then two
// independent GEMMs:
//   Xe = Xsum @ W1T  + deg_e*b1  -> XeOut (d_out)
//   Z  = Xsum @ W1Bf + deg_e*bZ  -> g_Z
// ---------------------------------------------------------------------------
__global__ __launch_bounds__(256) void k_edge_fused(const float* __restrict__ X,
                                                    const float* __restrict__ b1,
                                                    float* __restrict__ XeOut) {
    __shared__ float Xs[64][34];    // [k][r]
    __shared__ float W1s[64][64];
    __shared__ float W2s[64][64];
    __shared__ float bs[64], bzs[64], degs[32];
    int tid = threadIdx.x;
    int row0 = blockIdx.x * 32;

    for (int i = tid; i < 1024; i += 256) {
        ((float4*)W1s)[i] = ((const float4*)g_W1T)[i];
        ((float4*)W2s)[i] = ((const float4*)g_W1Bf)[i];
    }
    if (tid < 64) {
        bs[tid] = b1[tid];
        bzs[tid] = g_bZ[tid];
    } else if (tid < 96) {
        int r = row0 + tid - 64;
        degs[tid - 64] = (r < N_EDGES) ? (float)g_cur_e[r] : 0.f;
    }

    // gather phase: half-warp hw handles edges r = hw*2, hw*2+1
    int hw = tid >> 4, lane = tid & 15;
    const float4* X4 = (const float4*)X;
    #pragma unroll
    for (int sub = 0; sub < 2; sub++) {
        int r = hw * 2 + sub;
        int seg = row0 + r;
        float4 acc = make_float4(0.f, 0.f, 0.f, 0.f);
        if (seg < N_EDGES) {
            int d = g_cur_e[seg];
            if (d > ESTRIDE) d = ESTRIDE;
            acc = gather_rows(g_adj_e + seg * ESTRIDE, d, X4, lane);
        }
        Xs[lane * 4 + 0][r] = acc.x;
        Xs[lane * 4 + 1][r] = acc.y;
        Xs[lane * 4 + 2][r] = acc.z;
        Xs[lane * 4 + 3][r] = acc.w;
    }
    __syncthreads();

    int tx = tid & 15, ty = tid >> 4;   // 16 x 16
    int tx4 = tx * 4, ty2 = ty * 2;
    float a1[2][4] = {}, a2[2][4] = {};
    #pragma unroll 16
    for (int k = 0; k < 64; k++) {
        float2 a = *(const float2*)&Xs[k][ty2];
        float4 w1 = *(const float4*)&W1s[k][tx4];
        float4 w2 = *(const float4*)&W2s[k][tx4];
        a1[0][0] += a.x * w1.x; a1[0][1] += a.x * w1.y;
        a1[0][2] += a.x * w1.z; a1[0][3] += a.x * w1.w;
        a1[1][0] += a.y * w1.x; a1[1][1] += a.y * w1.y;
        a1[1][2] += a.y * w1.z; a1[1][3] += a.y * w1.w;
        a2[0][0] += a.x * w2.x; a2[0][1] += a.x * w2.y;
        a2[0][2] += a.x * w2.z; a2[0][3] += a.x * w2.w;
        a2[1][0] += a.y * w2.x; a2[1][1] += a.y * w2.y;
        a2[1][2] += a.y * w2.z; a2[1][3] += a.y * w2.w;
    }
    #pragma unroll
    for (int r = 0; r < 2; r++) {
        int row = row0 + ty2 + r;
        if (row < N_EDGES) {
            float dg = degs[ty2 + r];
            float4 xe = make_float4(a1[r][0] + dg * bs[tx4 + 0],
                                    a1[r][1] + dg * bs[tx4 + 1],
                                    a1[r][2] + dg * bs[tx4 + 2],
                                    a1[r][3] + dg * bs[tx4 + 3]);
            float4 z  = make_float4(a2[r][0] + dg * bzs[tx4 + 0],
                                    a2[r][1] + dg * bzs[tx4 + 1],
                                    a2[r][2] + dg * bzs[tx4 + 2],
                                    a2[r][3] + dg * bzs[tx4 + 3]);
            ((float4*)XeOut)[(size_t)row * 16 + tx] = xe;
            ((float4*)g_Z)[(size_t)row * 16 + tx]   = z;
        }
    }
}

// ---------------------------------------------------------------------------
// k_gather_v: SZ[v] = sum over adj_v[v] of Z[e]. Half-warp per vertex.
// ---------------------------------------------------------------------------
__global__ __launch_bounds__(256) void k_gather_v() {
    int t = threadIdx.x;
    int seg = blockIdx.x * 16 + (t >> 4);
    if (seg >= N_NODES) return;
    int lane = t & 15;
    int d = g_cur_v[seg];
    if (d > VSTRIDE) d = VSTRIDE;
    float4 acc = gather_rows(g_adj_v + seg * VSTRIDE, d, (const float4*)g_Z, lane);
    ((float4*)g_SZ)[(size_t)seg * 16 + lane] = acc;
}

// ---------------------------------------------------------------------------
// k_node_out (f32x2 packed FMA):
// out = 0.5*deg*(X@A) + 0.5*(X0@W^T) + 0.5*SZ + 0.5*deg*cvec + Wb
// ---------------------------------------------------------------------------
#define FMA_X2(d, a, b) \
    asm("fma.rn.f32x2 %0, %1, %2, %0;" : "+l"(d) : "l"(a), "l"(b))

#define XS_STRIDE 132   // floats per k-row; multiple of 4 -> 16B alignment kept

__global__ __launch_bounds__(256) void k_node_out(const float* __restrict__ X,
                                                  const float* __restrict__ X0,
                                                  const float* __restrict__ Wb,
                                                  float* __restrict__ out) {
    extern __shared__ char sm_raw[];
    float* Xs = (float*)sm_raw;                                        // [64][132]
    unsigned long long* Wd =
        (unsigned long long*)(sm_raw + 64 * XS_STRIDE * 4);            // [64][64] dup pairs
    float* degs = (float*)(sm_raw + 64 * XS_STRIDE * 4 + 64 * 64 * 8); // [128] = 0.5*deg
    float* cv   = degs + 128;                                          // [64]
    float* bb   = cv + 64;                                             // [64]

    int tid = threadIdx.x;
    int row0 = blockIdx.x * 128;

    if (tid < 128) {
        int r = row0 + tid;
        degs[tid] = (r < N_NODES) ? 0.5f * (float)g_cur_v[r] : 0.f;
    } else if (tid < 192) {
        cv[tid - 128] = g_cvec[tid - 128];
    } else {
        bb[tid - 192] = Wb[tid - 192];
    }
    __syncthreads();

    int tx = tid & 15, ty = tid >> 4;
    int tx4 = tx * 4, ty8 = ty * 8;

    unsigned long long acc[4][4];
    #pragma unroll
    for (int p = 0; p < 4; p++)
        #pragma unroll
        for (int c = 0; c < 4; c++) acc[p][c] = 0ULL;

    #pragma unroll
    for (int kb = 0; kb < 2; kb++) {
        const float* src = (kb == 0) ? X : X0;
        #pragma unroll
        for (int i = 0; i < 8; i++) {
            int f = tid + i * 256;
            int r = f >> 4, k4 = f & 15;
            int row = row0 + r;
            float s = (kb == 0) ? degs[r] : 0.5f;
            float4 x = (row < N_NODES) ? ((const float4*)src)[row * 16 + k4]
                                       : make_float4(0.f, 0.f, 0.f, 0.f);
            Xs[(k4 * 4 + 0) * XS_STRIDE + r] = s * x.x;
            Xs[(k4 * 4 + 1) * XS_STRIDE + r] = s * x.y;
            Xs[(k4 * 4 + 2) * XS_STRIDE + r] = s * x.z;
            Xs[(k4 * 4 + 3) * XS_STRIDE + r] = s * x.w;
        }
        for (int i = tid; i < 4096; i += 256) {
            float w = g_WcatA[kb * 4096 + i];
            ((float2*)Wd)[i] = make_float2(w, w);
        }
        __syncthreads();

        #pragma unroll 8
        for (int k = 0; k < 64; k++) {
            ulonglong2 a01 = *(const ulonglong2*)(Xs + k * XS_STRIDE + ty8);
            ulonglong2 a23 = *(const ulonglong2*)(Xs + k * XS_STRIDE + ty8 + 4);
            ulonglong2 b01 = *(const ulonglong2*)(Wd + k * 64 + tx4);
            ulonglong2 b23 = *(const ulonglong2*)(Wd + k * 64 + tx4 + 2);
            FMA_X2(acc[0][0], a01.x, b01.x); FMA_X2(acc[0][1], a01.x, b01.y);
            FMA_X2(acc[0][2], a01.x, b23.x); FMA_X2(acc[0][3], a01.x, b23.y);
            FMA_X2(acc[1][0], a01.y, b01.x); FMA_X2(acc[1][1], a01.y, b01.y);
            FMA_X2(acc[1][2], a01.y, b23.x); FMA_X2(acc[1][3], a01.y, b23.y);
            FMA_X2(acc[2][0], a23.x, b01.x); FMA_X2(acc[2][1], a23.x, b01.y);
            FMA_X2(acc[2][2], a23.x, b23.x); FMA_X2(acc[2][3], a23.x, b23.y);
            FMA_X2(acc[3][0], a23.y, b01.x); FMA_X2(acc[3][1], a23.y, b01.y);
            FMA_X2(acc[3][2], a23.y, b23.x); FMA_X2(acc[3][3], a23.y, b23.y);
        }
        __syncthreads();
    }

    const float4* SZ4 = (const float4*)g_SZ;
    #pragma unroll
    for (int p = 0; p < 4; p++) {
        float lo[4], hi[4];
        #pragma unroll
        for (int c = 0; c < 4; c++) {
            asm("mov.b64 {%0, %1}, %2;" : "=f"(lo[c]), "=f"(hi[c]) : "l"(acc[p][c]));
        }
        int rl = ty8 + 2 * p;
        int row_lo = row0 + rl;
        int row_hi = row_lo + 1;
        if (row_lo < N_NODES) {
            float hd = degs[rl];
            float4 sz = SZ4[(size_t)row_lo * 16 + tx];
            float4 o;
            o.x = lo[0] + 0.5f * sz.x + hd * cv[tx4 + 0] + bb[tx4 + 0];
            o.y = lo[1] + 0.5f * sz.y + hd * cv[tx4 + 1] + bb[tx4 + 1];
            o.z = lo[2] + 0.5f * sz.z + hd * cv[tx4 + 2] + bb[tx4 + 2];
            o.w = lo[3] + 0.5f * sz.w + hd * cv[tx4 + 3] + bb[tx4 + 3];
            ((float4*)out)[(size_t)row_lo * 16 + tx] = o;
        }
        if (row_hi < N_NODES) {
            float hd = degs[rl + 1];
            float4 sz = SZ4[(size_t)row_hi * 16 + tx];
            float4 o;
            o.x = hi[0] + 0.5f * sz.x + hd * cv[tx4 + 0] + bb[tx4 + 0];
            o.y = hi[1] + 0.5f * sz.y + hd * cv[tx4 + 1] + bb[tx4 + 1];
            o.z = hi[2] + 0.5f * sz.z + hd * cv[tx4 + 2] + bb[tx4 + 2];
            o.w = hi[3] + 0.5f * sz.w + hd * cv[tx4 + 3] + bb[tx4 + 3];
            ((float4*)out)[(size_t)row_hi * 16 + tx] = o;
        }
    }
}

#define NODE_SMEM (64 * XS_STRIDE * 4 + 64 * 64 * 8 + 128 * 4 + 64 * 4 + 64 * 4)

// ---------------------------------------------------------------------------
extern "C" void kernel_launch(void* const* d_in, const int* in_sizes, int n_in,
                              void* d_out, int out_size) {
    const float* X      = (const float*)d_in[0];
    const float* X0     = (const float*)d_in[1];
    const int*   vertex = (const int*)d_in[2];
    const int*   edges  = (const int*)d_in[3];
    const float* W1_w   = (const float*)d_in[4];
    const float* W1_b   = (const float*)d_in[5];
    const float* W2_w   = (const float*)d_in[6];
    const float* W2_b   = (const float*)d_in[7];
    const float* W_w    = (const float*)d_in[8];
    const float* W_b    = (const float*)d_in[9];

    float* out   = (float*)d_out;                       // [N_NODES, 64]
    float* XeOut = (float*)d_out + (size_t)N_NODES * D; // [N_EDGES, 64]

    static_assert(NODE_SMEM < 100 * 1024, "smem");
    cudaFuncSetAttribute(k_node_out, cudaFuncAttributeMaxDynamicSharedMemorySize,
                         NODE_SMEM);

    void *cureP = nullptr, *curvP = nullptr;
    cudaGetSymbolAddress(&cureP, g_cur_e);
    cudaGetSymbolAddress(&curvP, g_cur_v);
    cudaMemsetAsync(cureP, 0, (size_t)N_EDGES * sizeof(int), 0);
    cudaMemsetAsync(curvP, 0, (size_t)N_NODES * sizeof(int), 0);

    k_pre_all<<<1, 256>>>(W1_w, W1_b, W2_w, W2_b, W_w);
    k_fill<<<(NNZ / 2 + 255) / 256, 256>>>(vertex, edges);
    k_edge_fused<<<(N_EDGES + 31) / 32, 256>>>(X, W1_b, XeOut);
    k_gather_v<<<(N_NODES + 15) / 16, 256>>>();
    k_node_out<<<(N_NODES + 127) / 128, 256, NODE_SMEM>>>(X, X0, W_b, out);
}

// round 8
// speedup vs baseline: 1.4284x; 1.3582x over previous
#include <cuda_runtime.h>
#include <cstdint>

#define N_NODES 100000
#define N_EDGES 20000
#define NNZ     1000000
#define D       64
#define ESTRIDE 112          // max incidences per edge bin (Poisson(50), ~9 sigma)
#define VSTRIDE 40           // max incidences per vertex bin (Poisson(10), ~9 sigma)

#define NPRE    65           // pre blocks (16448 items / 256)
#define NFILL   1954         // fill blocks (500000 pair-threads / 256)
#define NPRE2   17           // pre2 blocks (4160 items / 256)
#define NGE     1250         // gather_e blocks (20000 edges / 16)
#define NGEMM   3125         // node gemm blocks (100000 rows / 32)

// ---------------- scratch (device globals; allocation-free) ----------------
__device__ int   g_cnt[N_EDGES + N_NODES];  // [0:E) edge counts, [E:) vertex counts
__device__ int   g_adj_e[N_EDGES * ESTRIDE];
__device__ int   g_adj_v[N_NODES * VSTRIDE];
__device__ float g_Xsum[N_EDGES * D];       // per-edge sum of X rows
__device__ float g_Z   [N_EDGES * D];       // Xsum @ W1Bf + deg*bZ
__device__ float g_P1  [N_NODES * D];       // 0.5*(X@A) + 0.5*cvec
__device__ float g_P2  [N_NODES * D];       // 0.5*(X0@W^T) + Wb
__device__ float g_W1T [D * D];             // W1_w transposed [k][j]
__device__ float g_Bf  [D * D];             // W2b^T @ W^T
__device__ float g_W1Bf[D * D];             // W1T @ Bf
__device__ float g_bZ  [D];                 // b1 @ Bf
__device__ float g_WcatA[128 * D];          // [A | W^T] stacked, [k][j]
__device__ float g_cvec[D];                 // b2 @ W^T

// ---------------------------------------------------------------------------
// fat1: blocks [0, NPRE) = weight folding stage 1; rest = adjacency fill.
// ---------------------------------------------------------------------------
__global__ __launch_bounds__(256) void k_fat1(const int* __restrict__ vertex,
                                              const int* __restrict__ edges,
                                              const float* __restrict__ W1_w,
                                              const float* __restrict__ W2_w,
                                              const float* __restrict__ W2_b,
                                              const float* __restrict__ W_w) {
    __shared__ float WT[64 * 64];   // WT[m][j] = W_w[j][m]
    int b = blockIdx.x;
    int tid = threadIdx.x;
    if (b < NPRE) {
        // ---- pre: A, W^T copy, Bf, W1T, cvec ----
        for (int i = tid; i < 4096; i += 256) {
            int j = i >> 6, m = i & 63;
            WT[m * 64 + j] = W_w[i];
        }
        __syncthreads();
        int idx = b * 256 + tid;
        if (idx < 4096) {                              // A = W2a^T @ W^T
            int k = idx >> 6, j = idx & 63;
            float acc = 0.f;
            #pragma unroll 8
            for (int m = 0; m < 64; m++) acc += W2_w[m * 128 + k] * WT[m * 64 + j];
            g_WcatA[idx] = acc;
        } else if (idx < 8192) {                       // W^T copy
            int t = idx - 4096;
            g_WcatA[4096 + t] = WT[t];
        } else if (idx < 12288) {                      // Bf = W2b^T @ W^T
            int t = idx - 8192;
            int k = t >> 6, j = t & 63;
            float acc = 0.f;
            #pragma unroll 8
            for (int m = 0; m < 64; m++) acc += W2_w[m * 128 + 64 + k] * WT[m * 64 + j];
            g_Bf[t] = acc;
        } else if (idx < 16384) {                      // W1T
            int t = idx - 12288;
            int k = t >> 6, j = t & 63;
            g_W1T[k * 64 + j] = W1_w[j * 64 + k];
        } else if (idx < 16448) {                      // cvec
            int j = idx - 16384;
            float acc = 0.f;
            for (int m = 0; m < 64; m++) acc += W2_b[m] * WT[m * 64 + j];
            g_cvec[j] = acc;
        }
    } else {
        // ---- fill: 2 incidences per thread ----
        int i = (b - NPRE) * 256 + tid;
        if (i >= NNZ / 2) return;
        int* cur_e = g_cnt;
        int* cur_v = g_cnt + N_EDGES;
        int2 v2 = __ldg((const int2*)vertex + i);
        int2 e2 = __ldg((const int2*)edges + i);
        int se0 = atomicAdd(&cur_e[e2.x], 1);
        if (se0 < ESTRIDE) g_adj_e[e2.x * ESTRIDE + se0] = v2.x;
        int sv0 = atomicAdd(&cur_v[v2.x], 1);
        if (sv0 < VSTRIDE) g_adj_v[v2.x * VSTRIDE + sv0] = e2.x;
        int se1 = atomicAdd(&cur_e[e2.y], 1);
        if (se1 < ESTRIDE) g_adj_e[e2.y * ESTRIDE + se1] = v2.y;
        int sv1 = atomicAdd(&cur_v[v2.y], 1);
        if (sv1 < VSTRIDE) g_adj_v[v2.y * VSTRIDE + sv1] = e2.y;
    }
}

// float4 gather-accumulate helper (unroll 4)
__device__ __forceinline__ float4 gather_rows(const int* __restrict__ adj, int d,
                                              const float4* __restrict__ S4,
                                              int lane) {
    float4 acc = make_float4(0.f, 0.f, 0.f, 0.f);
    int j = 0;
    for (; j + 4 <= d; j += 4) {
        int a0 = __ldg(adj + j + 0);
        int a1 = __ldg(adj + j + 1);
        int a2 = __ldg(adj + j + 2);
        int a3 = __ldg(adj + j + 3);
        float4 x0 = S4[(size_t)a0 * 16 + lane];
        float4 x1 = S4[(size_t)a1 * 16 + lane];
        float4 x2 = S4[(size_t)a2 * 16 + lane];
        float4 x3 = S4[(size_t)a3 * 16 + lane];
        acc.x += (x0.x + x1.x) + (x2.x + x3.x);
        acc.y += (x0.y + x1.y) + (x2.y + x3.y);
        acc.z += (x0.z + x1.z) + (x2.z + x3.z);
        acc.w += (x0.w + x1.w) + (x2.w + x3.w);
    }
    for (; j < d; j++) {
        int a0 = __ldg(adj + j);
        float4 x0 = S4[(size_t)a0 * 16 + lane];
        acc.x += x0.x; acc.y += x0.y; acc.z += x0.z; acc.w += x0.w;
    }
    return acc;
}

#define FMA_X2(d, a, b) \
    asm("fma.rn.f32x2 %0, %1, %2, %0;" : "+l"(d) : "l"(a), "l"(b))
#define PACK2(d, v) \
    asm("mov.b64 %0, {%1, %1};" : "=l"(d) : "f"(v))

// ---------------------------------------------------------------------------
// fat2: blocks [0,NPRE2) = pre2 (W1Bf, bZ); [NPRE2, NPRE2+NGE) = gather_e;
//       rest = node GEMM (P1 = 0.5*X@A + 0.5*cvec, P2 = 0.5*X0@W^T + Wb).
// ---------------------------------------------------------------------------
__global__ __launch_bounds__(256) void k_fat2(const float* __restrict__ X,
                                              const float* __restrict__ X0,
                                              const float* __restrict__ W1_b,
                                              const float* __restrict__ Wb) {
    __shared__ float Xs[64][34];    // [k][r] 32-row tile (8.7KB)
    __shared__ float Ws[64 * 64];   // weights (16KB); pre2 reuses as Bf
    __shared__ float cvs[64];
    __shared__ float bbs[64];

    int b = blockIdx.x;
    int tid = threadIdx.x;

    if (b < NPRE2) {
        // ---- pre2: W1Bf = W1T @ Bf, bZ = b1 @ Bf ----
        for (int i = tid; i < 4096; i += 256) Ws[i] = g_Bf[i];
        __syncthreads();
        int idx = b * 256 + tid;
        if (idx < 4096) {
            int k = idx >> 6, j = idx & 63;
            float acc = 0.f;
            #pragma unroll 8
            for (int m = 0; m < 64; m++) acc += __ldg(g_W1T + k * 64 + m) * Ws[m * 64 + j];
            g_W1Bf[idx] = acc;
        } else if (idx < 4160) {
            int j = idx - 4096;
            float acc = 0.f;
            for (int m = 0; m < 64; m++) acc += __ldg(W1_b + m) * Ws[m * 64 + j];
            g_bZ[j] = acc;
        }
        return;
    }
    if (b < NPRE2 + NGE) {
        // ---- gather_e: one edge per half-warp ----
        int seg = (b - NPRE2) * 16 + (tid >> 4);
        int lane = tid & 15;
        int d = g_cnt[seg];
        if (d > ESTRIDE) d = ESTRIDE;
        float4 acc = gather_rows(g_adj_e + seg * ESTRIDE, d, (const float4*)X, lane);
        ((float4*)g_Xsum)[(size_t)seg * 16 + lane] = acc;
        return;
    }

    // ---- node GEMM: 32-row tile, two phases ----
    int row0 = (b - NPRE2 - NGE) * 32;
    if (tid < 64) cvs[tid] = 0.5f * g_cvec[tid];
    else if (tid < 128) bbs[tid - 64] = Wb[tid - 64];

    int tx = tid & 15, ty = tid >> 4;
    int tx4 = tx * 4, ty2 = ty * 2;

    #pragma unroll
    for (int ph = 0; ph < 2; ph++) {
        const float* src = (ph == 0) ? X : X0;
        // load input tile transposed + pre-scaled by 0.5: Xs[k][r]
        #pragma unroll
        for (int i = 0; i < 2; i++) {
            int f = tid + i * 256;
            int r = f >> 4, k4 = f & 15;
            float4 x = ((const float4*)src)[(size_t)(row0 + r) * 16 + k4];
            Xs[k4 * 4 + 0][r] = 0.5f * x.x;
            Xs[k4 * 4 + 1][r] = 0.5f * x.y;
            Xs[k4 * 4 + 2][r] = 0.5f * x.z;
            Xs[k4 * 4 + 3][r] = 0.5f * x.w;
        }
        const float4* wsrc = (const float4*)(g_WcatA + ph * 4096);
        #pragma unroll
        for (int i = 0; i < 4; i++)
            ((float4*)Ws)[tid + i * 256] = wsrc[tid + i * 256];
        __syncthreads();

        unsigned long long acc[4] = {0ULL, 0ULL, 0ULL, 0ULL};
        #pragma unroll 16
        for (int k = 0; k < 64; k++) {
            unsigned long long apair = *(const unsigned long long*)&Xs[k][ty2];
            float4 w = *(const float4*)&Ws[k * 64 + tx4];
            unsigned long long b0, b1, b2, b3;
            PACK2(b0, w.x); PACK2(b1, w.y); PACK2(b2, w.z); PACK2(b3, w.w);
            FMA_X2(acc[0], apair, b0);
            FMA_X2(acc[1], apair, b1);
            FMA_X2(acc[2], apair, b2);
            FMA_X2(acc[3], apair, b3);
        }

        float lo[4], hi[4];
        #pragma unroll
        for (int c = 0; c < 4; c++)
            asm("mov.b64 {%0, %1}, %2;" : "=f"(lo[c]), "=f"(hi[c]) : "l"(acc[c]));
        float* dst = (ph == 0) ? g_P1 : g_P2;
        float add0 = (ph == 0) ? cvs[tx4 + 0] : bbs[tx4 + 0];
        float add1 = (ph == 0) ? cvs[tx4 + 1] : bbs[tx4 + 1];
        float add2 = (ph == 0) ? cvs[tx4 + 2] : bbs[tx4 + 2];
        float add3 = (ph == 0) ? cvs[tx4 + 3] : bbs[tx4 + 3];
        int row = row0 + ty2;
        float4 o0 = make_float4(lo[0] + add0, lo[1] + add1, lo[2] + add2, lo[3] + add3);
        float4 o1 = make_float4(hi[0] + add0, hi[1] + add1, hi[2] + add2, hi[3] + add3);
        ((float4*)dst)[(size_t)row * 16 + tx] = o0;
        ((float4*)dst)[(size_t)(row + 1) * 16 + tx] = o1;
        __syncthreads();   // before Xs/Ws reload
    }
}

// ---------------------------------------------------------------------------
// k_edge_gemm: two independent GEMMs from the Xsum tile:
//   Xe = Xsum @ W1T  + deg_e*b1  -> XeOut (d_out)
//   Z  = Xsum @ W1Bf + deg_e*bZ  -> g_Z
// ---------------------------------------------------------------------------
__global__ __launch_bounds__(256) void k_edge_gemm(const float* __restrict__ b1,
                                                   float* __restrict__ XeOut) {
    __shared__ float Xs[64][34];
    __shared__ float W1s[64][64];
    __shared__ float W2s[64][64];
    __shared__ float bs[64], bzs[64], degs[32];
    int tid = threadIdx.x;
    int row0 = blockIdx.x * 32;

    for (int i = tid; i < 1024; i += 256) {
        ((float4*)W1s)[i] = ((const float4*)g_W1T)[i];
        ((float4*)W2s)[i] = ((const float4*)g_W1Bf)[i];
    }
    if (tid < 64) {
        bs[tid] = b1[tid];
        bzs[tid] = g_bZ[tid];
    } else if (tid < 96) {
        int r = row0 + tid - 64;
        degs[tid - 64] = (r < N_EDGES) ? (float)g_cnt[r] : 0.f;
    }
    #pragma unroll
    for (int i = 0; i < 2; i++) {
        int f = tid + i * 256;
        int r = f >> 4, k4 = f & 15;
        int row = row0 + r;
        float4 x = (row < N_EDGES) ? ((const float4*)g_Xsum)[row * 16 + k4]
                                   : make_float4(0.f, 0.f, 0.f, 0.f);
        Xs[k4 * 4 + 0][r] = x.x; Xs[k4 * 4 + 1][r] = x.y;
        Xs[k4 * 4 + 2][r] = x.z; Xs[k4 * 4 + 3][r] = x.w;
    }
    __syncthreads();

    int tx = tid & 15, ty = tid >> 4;
    int tx4 = tx * 4, ty2 = ty * 2;
    float a1[2][4] = {}, a2[2][4] = {};
    #pragma unroll 16
    for (int k = 0; k < 64; k++) {
        float2 a = *(const float2*)&Xs[k][ty2];
        float4 w1 = *(const float4*)&W1s[k][tx4];
        float4 w2 = *(const float4*)&W2s[k][tx4];
        a1[0][0] += a.x * w1.x; a1[0][1] += a.x * w1.y;
        a1[0][2] += a.x * w1.z; a1[0][3] += a.x * w1.w;
        a1[1][0] += a.y * w1.x; a1[1][1] += a.y * w1.y;
        a1[1][2] += a.y * w1.z; a1[1][3] += a.y * w1.w;
        a2[0][0] += a.x * w2.x; a2[0][1] += a.x * w2.y;
        a2[0][2] += a.x * w2.z; a2[0][3] += a.x * w2.w;
        a2[1][0] += a.y * w2.x; a2[1][1] += a.y * w2.y;
        a2[1][2] += a.y * w2.z; a2[1][3] += a.y * w2.w;
    }
    #pragma unroll
    for (int r = 0; r < 2; r++) {
        int row = row0 + ty2 + r;
        if (row < N_EDGES) {
            float dg = degs[ty2 + r];
            float4 xe = make_float4(a1[r][0] + dg * bs[tx4 + 0],
                                    a1[r][1] + dg * bs[tx4 + 1],
                                    a1[r][2] + dg * bs[tx4 + 2],
                                    a1[r][3] + dg * bs[tx4 + 3]);
            float4 z  = make_float4(a2[r][0] + dg * bzs[tx4 + 0],
                                    a2[r][1] + dg * bzs[tx4 + 1],
                                    a2[r][2] + dg * bzs[tx4 + 2],
                                    a2[r][3] + dg * bzs[tx4 + 3]);
            ((float4*)XeOut)[(size_t)row * 16 + tx] = xe;
            ((float4*)g_Z)[(size_t)row * 16 + tx]   = z;
        }
    }
}

// ---------------------------------------------------------------------------
// k_gatherv_out: out[v] = deg_v * P1[v] + P2[v] + 0.5 * sum(Z[e] over adj_v[v])
// One node per half-warp.
// ---------------------------------------------------------------------------
__global__ __launch_bounds__(256) void k_gatherv_out(float* __restrict__ out) {
    int t = threadIdx.x;
    int seg = blockIdx.x * 16 + (t >> 4);
    int lane = t & 15;
    int dtrue = g_cnt[N_EDGES + seg];
    int d = dtrue > VSTRIDE ? VSTRIDE : dtrue;
    float4 acc = gather_rows(g_adj_v + seg * VSTRIDE, d, (const float4*)g_Z, lane);
    float deg = (float)dtrue;
    float4 p1 = ((const float4*)g_P1)[(size_t)seg * 16 + lane];
    float4 p2 = ((const float4*)g_P2)[(size_t)seg * 16 + lane];
    float4 o;
    o.x = deg * p1.x + p2.x + 0.5f * acc.x;
    o.y = deg * p1.y + p2.y + 0.5f * acc.y;
    o.z = deg * p1.z + p2.z + 0.5f * acc.z;
    o.w = deg * p1.w + p2.w + 0.5f * acc.w;
    ((float4*)out)[(size_t)seg * 16 + lane] = o;
}

// ---------------------------------------------------------------------------
extern "C" void kernel_launch(void* const* d_in, const int* in_sizes, int n_in,
                              void* d_out, int out_size) {
    const float* X      = (const float*)d_in[0];
    const float* X0     = (const float*)d_in[1];
    const int*   vertex = (const int*)d_in[2];
    const int*   edges  = (const int*)d_in[3];
    const float* W1_w   = (const float*)d_in[4];
    const float* W1_b   = (const float*)d_in[5];
    const float* W2_w   = (const float*)d_in[6];
    const float* W2_b   = (const float*)d_in[7];
    const float* W_w    = (const float*)d_in[8];
    const float* W_b    = (const float*)d_in[9];

    float* out   = (float*)d_out;                       // [N_NODES, 64]
    float* XeOut = (float*)d_out + (size_t)N_NODES * D; // [N_EDGES, 64]

    void* cntP = nullptr;
    cudaGetSymbolAddress(&cntP, g_cnt);
    cudaMemsetAsync(cntP, 0, (size_t)(N_EDGES + N_NODES) * sizeof(int), 0);

    k_fat1<<<NPRE + NFILL, 256>>>(vertex, edges, W1_w, W2_w, W2_b, W_w);
    k_fat2<<<NPRE2 + NGE + NGEMM, 256>>>(X, X0, W1_b, W_b);
    k_edge_gemm<<<(N_EDGES + 31) / 32, 256>>>(W1_b, XeOut);
    k_gatherv_out<<<N_NODES / 16, 256>>>(out);
}